// round 16
// baseline (speedup 1.0000x reference)
#include <cuda_runtime.h>
#include <math.h>
#include <stdint.h>

#define THREADS 256
#define TT      16
#define N_TOK   65536
#define NCTA    (N_TOK / TT)     // 4096
#define DM      128
#define HID     256
#define NN      17
#define NF      32
#define ND      544              // 17*32

#define NSY  548                 // ns row stride (floats)
#define HPLW 132                 // h-plane row stride (u32 words)
#define XPW  68                  // x-plane row stride (u32 words)
#define MPLW 18                  // mixed-plane row stride (u32 words)
#define MROWS 144                // 136 real rows (8 tok * 17) + 8 pad rows

// ---- smem layout (floats) ----
#define OFF_NS   0
#define SZ_NS    (TT * NSY)            // 8768
#define OFF_WB   (OFF_NS + SZ_NS)      // 8768
#define SZ_WB    (2 * MROWS * MPLW)    // 5184 (>= 2*16*132=4224 h planes)
#define OFF_ADJ  (OFF_WB + SZ_WB)      // 13952
#define SZ_ADJ   292
#define SMEM_FLOATS (OFF_ADJ + SZ_ADJ) // 14244 floats = 56976 B  (3 CTAs/SM)

// pre-split weights in fragment-packed layout: {hi0, hi1, lo0, lo1} per lane
__device__ uint4 g_w1p[16 * 8 * 2 * 32];    // group = (j*8+kc)*2+fi
__device__ uint4 g_w2p[34 * 16 * 2 * 32];   // group = (j*16+kc)*2+fi
__device__ uint4 g_wgp[2 * 2 * 4 * 32];     // group = ((layer*2+kc)*4+nf)
__device__ float g_adj[2 * NN * NN];        // softmaxed adjacency per layer

__device__ __forceinline__ float gelu_f(float v) {
    return 0.5f * v * (1.0f + erff(v * 0.7071067811865476f));
}

// split a k-pair (v0 = even k, v1 = odd k) into packed bf16x2 hi and lo words.
__device__ __forceinline__ void pair_split(float v0, float v1, uint32_t& hi, uint32_t& lo) {
    uint32_t h;
    asm("cvt.rn.bf16x2.f32 %0, %1, %2;" : "=r"(h) : "f"(v1), "f"(v0));
    float h0 = __uint_as_float(h << 16);
    float h1 = __uint_as_float(h & 0xffff0000u);
    asm("cvt.rn.bf16x2.f32 %0, %1, %2;" : "=r"(lo) : "f"(v1 - h1), "f"(v0 - h0));
    hi = h;
}

// m16n8k16 bf16 MMA, fp32 accumulate
__device__ __forceinline__ void mma_bf16(float* d, const uint32_t* a, const uint32_t* b) {
    asm volatile(
        "mma.sync.aligned.m16n8k16.row.col.f32.bf16.bf16.f32 "
        "{%0,%1,%2,%3}, {%4,%5,%6,%7}, {%8,%9}, {%0,%1,%2,%3};"
        : "+f"(d[0]), "+f"(d[1]), "+f"(d[2]), "+f"(d[3])
        : "r"(a[0]), "r"(a[1]), "r"(a[2]), "r"(a[3]), "r"(b[0]), "r"(b[1]));
}

// ---------------- prologue: pack W1/W2/Wg frags + adj softmax ----------------
extern "C" __global__ void __launch_bounds__(256)
split_weights_kernel(const float* __restrict__ W1, const float* __restrict__ W2,
                     const float* __restrict__ Wg1, const float* __restrict__ Wg2,
                     const float* __restrict__ adj1, const float* __restrict__ adj2)
{
    const int idx  = blockIdx.x * 256 + threadIdx.x;
    const int grp  = idx >> 5;
    const int lane = idx & 31;
    const int g    = lane >> 2;
    const int tg   = lane & 3;
    if (grp < 256) {                                   // W1: j(16) kc(8) fi(2)
        const int fi = grp & 1, kc = (grp >> 1) & 7, j = grp >> 4;
        const int col = 16 * j + 8 * fi + g;
        const int k0  = 16 * kc + 2 * tg;
        uint32_t h0, l0, h1, l1;
        pair_split(W1[k0 * HID + col],       W1[(k0 + 1) * HID + col], h0, l0);
        pair_split(W1[(k0 + 8) * HID + col], W1[(k0 + 9) * HID + col], h1, l1);
        uint4 v; v.x = h0; v.y = h1; v.z = l0; v.w = l1;
        g_w1p[grp * 32 + lane] = v;
    } else if (grp < 256 + 1088) {                     // W2: j(34) kc(16) fi(2)
        const int g2 = grp - 256;
        const int fi = g2 & 1, kc = (g2 >> 1) & 15, j = g2 >> 5;
        const int col = 16 * j + 8 * fi + g;
        const int k0  = 16 * kc + 2 * tg;
        uint32_t h0, l0, h1, l1;
        pair_split(W2[(size_t)k0 * ND + col],       W2[(size_t)(k0 + 1) * ND + col], h0, l0);
        pair_split(W2[(size_t)(k0 + 8) * ND + col], W2[(size_t)(k0 + 9) * ND + col], h1, l1);
        uint4 v; v.x = h0; v.y = h1; v.z = l0; v.w = l1;
        g_w2p[g2 * 32 + lane] = v;
    } else if (grp < 1344 + 16) {                      // Wg frags: layer(2) kc(2) nf(4)
        const int gg = grp - 1344;
        const int nf = gg & 3, kc = (gg >> 2) & 1, layer = gg >> 3;
        const float* Wg = layer ? Wg2 : Wg1;
        const int col = 8 * nf + g;
        const int k0  = 16 * kc + 2 * tg;
        uint32_t h0, l0, h1, l1;
        pair_split(Wg[k0 * NF + col],       Wg[(k0 + 1) * NF + col], h0, l0);
        pair_split(Wg[(k0 + 8) * NF + col], Wg[(k0 + 9) * NF + col], h1, l1);
        uint4 v; v.x = h0; v.y = h1; v.z = l0; v.w = l1;
        g_wgp[gg * 32 + lane] = v;
    } else if (grp < 1362) {                           // adj softmax rows
        const int layer = grp - 1360;
        const float* aG = layer ? adj2 : adj1;
        if (lane < NN) {
            float r[NN];
            float mx = -3.0e38f;
            #pragma unroll
            for (int j = 0; j < NN; j++) { r[j] = aG[lane * NN + j]; mx = fmaxf(mx, r[j]); }
            float s = 0.0f;
            #pragma unroll
            for (int j = 0; j < NN; j++) { r[j] = expf(r[j] - mx); s += r[j]; }
            float inv = 1.0f / s;
            #pragma unroll
            for (int j = 0; j < NN; j++) g_adj[layer * 289 + lane * NN + j] = r[j] * inv;
        }
    }
}

// ---------------- GAT layer: 8 warps, 2 quarters of 8 tokens ----------------
template<bool FINAL>
__device__ __forceinline__ void gat_layer(
    float* __restrict__ ns, uint32_t* __restrict__ mh, uint32_t* __restrict__ ml,
    float* __restrict__ adjs,
    const float* __restrict__ adjP, const uint4* __restrict__ wgp,
    const float* __restrict__ bgG,
    const float* __restrict__ Wc, const float* __restrict__ bc,
    float* __restrict__ outp, int tid)
{
    const int lane = tid & 31;
    const int wid  = tid >> 5;     // 0..7
    const int g    = lane >> 2;
    const int tg   = lane & 3;

    for (int i = tid; i < NN * NN; i += THREADS) adjs[i] = adjP[i];

    float bgr[4][2];
    #pragma unroll
    for (int nf = 0; nf < 4; nf++) {
        bgr[nf][0] = bgG[8 * nf + 2 * tg];
        bgr[nf][1] = bgG[8 * nf + 2 * tg + 1];
    }
    __syncthreads();   // adjs ready; orders previous phase's ns writes / plane pad

    const int pp   = lane >> 1;
    const int slot = (pp >> 3) * 8 + 2 * (pp & 3) + ((pp & 7) >> 2);

    #pragma unroll 1
    for (int q = 0; q < 2; q++) {
        // ---- mixed: token t = q*8 + wid -> split bf16 plane rows wid*17.. ----
        {
            const float* nt = ns + (q * 8 + wid) * NSY;
            float nr[NN];
            #pragma unroll
            for (int j = 0; j < NN; j++) nr[j] = nt[j * NF + lane];
            const int rbase = wid * NN;
            #pragma unroll 1
            for (int i = 0; i < NN; i++) {
                const float* ar = adjs + i * NN;
                float m = 0.0f;
                #pragma unroll
                for (int j = 0; j < NN; j++) m += ar[j] * nr[j];
                const float v = __shfl_xor_sync(0xffffffffu, m, 1);
                if (!(lane & 1)) {
                    uint32_t hi, lo;
                    pair_split(m, v, hi, lo);
                    mh[(rbase + i) * MPLW + slot] = hi;
                    ml[(rbase + i) * MPLW + slot] = lo;
                }
            }
        }
        __syncthreads();

        // ---- GEMM [136(+8 pad) x 32] @ Wg[32x32] (bf16x3) + fused epilogue ----
        #pragma unroll 1
        for (int mi = wid; mi < 9; mi += 8) {
            float d[4][4] = {};
            const int r0 = 16 * mi + g;
            #pragma unroll
            for (int kc = 0; kc < 2; kc++) {
                const int base = kc * 8 + 2 * tg;
                uint32_t ah[4], al[4];
                uint2 q0, q1;
                q0 = *reinterpret_cast<const uint2*>(mh + r0 * MPLW + base);
                q1 = *reinterpret_cast<const uint2*>(mh + (r0 + 8) * MPLW + base);
                ah[0] = q0.x; ah[2] = q0.y; ah[1] = q1.x; ah[3] = q1.y;
                q0 = *reinterpret_cast<const uint2*>(ml + r0 * MPLW + base);
                q1 = *reinterpret_cast<const uint2*>(ml + (r0 + 8) * MPLW + base);
                al[0] = q0.x; al[2] = q0.y; al[1] = q1.x; al[3] = q1.y;
                #pragma unroll
                for (int nf = 0; nf < 4; nf++) {
                    uint4 bw = wgp[(kc * 4 + nf) * 32 + lane];
                    uint32_t bh[2], bl[2];
                    bh[0] = bw.x; bh[1] = bw.y; bl[0] = bw.z; bl[1] = bw.w;
                    mma_bf16(d[nf], ah, bh);
                    mma_bf16(d[nf], al, bh);
                    mma_bf16(d[nf], ah, bl);
                }
            }
            // epilogue: rows rg0 (always valid) and rg1 (pad-guarded)
            const int rg0 = r0;            // <= 135
            const int rg1 = r0 + 8;        // may be pad (>=136)
            const bool v1 = (rg1 < 136);
            const int t0i = rg0 / NN, i0 = rg0 - t0i * NN;
            const int t1r = v1 ? rg1 : rg0;
            const int t1i = t1r / NN, i1 = t1r - t1i * NN;
            float* p0base = ns + (q * 8 + t0i) * NSY + i0 * NF;
            float* p1base = ns + (q * 8 + t1i) * NSY + i1 * NF;   // clamped if pad
            if (!FINAL) {
                #pragma unroll
                for (int nf = 0; nf < 4; nf++) {
                    const int c0 = 8 * nf + 2 * tg;
                    float2 rv0 = *reinterpret_cast<float2*>(p0base + c0);
                    float2 rv1 = *reinterpret_cast<float2*>(p1base + c0);
                    float2 o0, o1;
                    o0.x = gelu_f(d[nf][0] + bgr[nf][0]) + rv0.x;
                    o0.y = gelu_f(d[nf][1] + bgr[nf][1]) + rv0.y;
                    o1.x = gelu_f(d[nf][2] + bgr[nf][0]) + rv1.x;
                    o1.y = gelu_f(d[nf][3] + bgr[nf][1]) + rv1.y;
                    *reinterpret_cast<float2*>(p0base + c0) = o0;
                    if (v1) *reinterpret_cast<float2*>(p1base + c0) = o1;
                }
            } else {
                float wcr[4][2][2];
                #pragma unroll
                for (int nf = 0; nf < 4; nf++)
                    #pragma unroll
                    for (int jj = 0; jj < 2; jj++) {
                        wcr[nf][jj][0] = Wc[(8 * nf + 2 * tg + jj) * 2];
                        wcr[nf][jj][1] = Wc[(8 * nf + 2 * tg + jj) * 2 + 1];
                    }
                float s00 = 0.0f, s01 = 0.0f, s10 = 0.0f, s11 = 0.0f;
                #pragma unroll
                for (int nf = 0; nf < 4; nf++) {
                    const int c0 = 8 * nf + 2 * tg;
                    float2 rv0 = *reinterpret_cast<float2*>(p0base + c0);
                    float2 rv1 = *reinterpret_cast<float2*>(p1base + c0);
                    const float v0 = gelu_f(d[nf][0] + bgr[nf][0]) + rv0.x;
                    const float vb = gelu_f(d[nf][1] + bgr[nf][1]) + rv0.y;
                    const float v2 = gelu_f(d[nf][2] + bgr[nf][0]) + rv1.x;
                    const float v3 = gelu_f(d[nf][3] + bgr[nf][1]) + rv1.y;
                    s00 += v0 * wcr[nf][0][0] + vb * wcr[nf][1][0];
                    s01 += v0 * wcr[nf][0][1] + vb * wcr[nf][1][1];
                    s10 += v2 * wcr[nf][0][0] + v3 * wcr[nf][1][0];
                    s11 += v2 * wcr[nf][0][1] + v3 * wcr[nf][1][1];
                }
                #pragma unroll
                for (int off = 1; off <= 2; off <<= 1) {
                    s00 += __shfl_xor_sync(0xffffffffu, s00, off);
                    s01 += __shfl_xor_sync(0xffffffffu, s01, off);
                    s10 += __shfl_xor_sync(0xffffffffu, s10, off);
                    s11 += __shfl_xor_sync(0xffffffffu, s11, off);
                }
                if (tg == 0) {
                    float2 o0; o0.x = s00 + bc[0]; o0.y = s01 + bc[1];
                    *reinterpret_cast<float2*>(outp + (q * 8 + t0i) * (NN * 2) + i0 * 2) = o0;
                    if (v1) {
                        float2 o1; o1.x = s10 + bc[0]; o1.y = s11 + bc[1];
                        *reinterpret_cast<float2*>(outp + (q * 8 + t1i) * (NN * 2) + i1 * 2) = o1;
                    }
                }
            }
        }
        __syncthreads();
    }
}

// ---------------- fused main kernel ----------------
extern "C" __global__ void __launch_bounds__(THREADS, 3)
biogat_kernel(const float* __restrict__ x,
              const float* __restrict__ b1,  const float* __restrict__ b2,
              const float* __restrict__ bg1, const float* __restrict__ bg2,
              const float* __restrict__ Wc,  const float* __restrict__ bc,
              float* __restrict__ out)
{
    extern __shared__ float sh[];
    float* ns   = sh + OFF_NS;
    float* wbr  = sh + OFF_WB;
    float* adjs = sh + OFF_ADJ;

    uint32_t* hh = reinterpret_cast<uint32_t*>(wbr);
    uint32_t* hl = hh + TT * HPLW;               // h planes (dead once GAT starts)
    uint32_t* mh = reinterpret_cast<uint32_t*>(wbr);
    uint32_t* ml = mh + MROWS * MPLW;            // mixed planes

    uint32_t* xh = reinterpret_cast<uint32_t*>(sh + OFF_NS);
    uint32_t* xl = xh + TT * XPW;                // x planes (alias ns)

    const int tid  = threadIdx.x;
    const int w    = tid >> 5;    // 0..7
    const int lane = tid & 31;
    const int g    = lane >> 2;
    const int tg   = lane & 3;
    const int tok0 = blockIdx.x * TT;

    // ---- stage + split x into fragment-permuted bf16 hi/lo planes ----
    {
        const float2* xg = reinterpret_cast<const float2*>(x + (size_t)tok0 * DM);
        #pragma unroll
        for (int it = 0; it < (TT * 64) / THREADS; it++) {
            const int p = tid + it * THREADS;
            const int r = p >> 6, q = p & 63;
            float2 v = xg[p];
            uint32_t hi, lo; pair_split(v.x, v.y, hi, lo);
            const int slot = (q >> 3) * 8 + 2 * (q & 3) + ((q & 7) >> 2);
            xh[r * XPW + slot] = hi;
            xl[r * XPW + slot] = lo;
        }
    }
    __syncthreads();

    // ================= phase 1: h = gelu(x @ W1 + b1) =================
    #pragma unroll 1
    for (int pp = 0; pp < 2; pp++) {
        const int n0c = w + 8 * pp;              // k-chunk / 16-col job
        float d[2][4] = {};
        #pragma unroll 1
        for (int kc = 0; kc < 8; kc++) {
            const int base = kc * 8 + 2 * tg;
            uint32_t ah[4], al[4];
            uint2 t0, t1;
            t0 = *reinterpret_cast<const uint2*>(xh + g * XPW + base);
            t1 = *reinterpret_cast<const uint2*>(xh + (g + 8) * XPW + base);
            ah[0] = t0.x; ah[2] = t0.y; ah[1] = t1.x; ah[3] = t1.y;
            t0 = *reinterpret_cast<const uint2*>(xl + g * XPW + base);
            t1 = *reinterpret_cast<const uint2*>(xl + (g + 8) * XPW + base);
            al[0] = t0.x; al[2] = t0.y; al[1] = t1.x; al[3] = t1.y;
            #pragma unroll
            for (int fi = 0; fi < 2; fi++) {
                uint4 bw = g_w1p[((n0c * 8 + kc) * 2 + fi) * 32 + lane];
                uint32_t bh[2], bl[2];
                bh[0] = bw.x; bh[1] = bw.y; bl[0] = bw.z; bl[1] = bw.w;
                mma_bf16(d[fi], ah, bh);
                mma_bf16(d[fi], al, bh);
                mma_bf16(d[fi], ah, bl);
            }
        }
        const int n0 = 16 * n0c;
        const float2 bv0 = *reinterpret_cast<const float2*>(b1 + n0 + 2 * tg);
        const float2 bv1 = *reinterpret_cast<const float2*>(b1 + n0 + 8 + 2 * tg);
        #pragma unroll
        for (int half = 0; half < 2; half++) {
            const int row = g + 8 * half;
            uint32_t hw0, lw0, hw1, lw1;
            pair_split(gelu_f(d[0][2*half]   + bv0.x),
                       gelu_f(d[0][2*half+1] + bv0.y), hw0, lw0);
            pair_split(gelu_f(d[1][2*half]   + bv1.x),
                       gelu_f(d[1][2*half+1] + bv1.y), hw1, lw1);
            const int widx = row * HPLW + n0c * 8 + 2 * tg;
            uint2 hv; hv.x = hw0; hv.y = hw1;
            uint2 lv; lv.x = lw0; lv.y = lw1;
            *reinterpret_cast<uint2*>(hh + widx) = hv;
            *reinterpret_cast<uint2*>(hl + widx) = lv;
        }
    }
    __syncthreads();

    // ================= phase 2: nodes = h @ W2 + b2 =================
    #pragma unroll 1
    for (int j = w; j < 34; j += 8) {
        float d[2][4] = {};
        #pragma unroll 1
        for (int kc = 0; kc < 16; kc++) {
            const int base = kc * 8 + 2 * tg;
            uint32_t ah[4], al[4];
            uint2 t0, t1;
            t0 = *reinterpret_cast<const uint2*>(hh + g * HPLW + base);
            t1 = *reinterpret_cast<const uint2*>(hh + (g + 8) * HPLW + base);
            ah[0] = t0.x; ah[2] = t0.y; ah[1] = t1.x; ah[3] = t1.y;
            t0 = *reinterpret_cast<const uint2*>(hl + g * HPLW + base);
            t1 = *reinterpret_cast<const uint2*>(hl + (g + 8) * HPLW + base);
            al[0] = t0.x; al[2] = t0.y; al[1] = t1.x; al[3] = t1.y;
            #pragma unroll
            for (int nf = 0; nf < 2; nf++) {
                uint4 bw = g_w2p[((j * 16 + kc) * 2 + nf) * 32 + lane];
                uint32_t bh[2], bl[2];
                bh[0] = bw.x; bh[1] = bw.y; bl[0] = bw.z; bl[1] = bw.w;
                mma_bf16(d[nf], ah, bh);
                mma_bf16(d[nf], al, bh);
                mma_bf16(d[nf], ah, bl);
            }
        }
        #pragma unroll
        for (int nf = 0; nf < 2; nf++) {
            const int c0 = 16 * j + 8 * nf + 2 * tg;
            const float2 bv = *reinterpret_cast<const float2*>(b2 + c0);
            float2 o0, o1;
            o0.x = d[nf][0] + bv.x;
            o0.y = d[nf][1] + bv.y;
            o1.x = d[nf][2] + bv.x;
            o1.y = d[nf][3] + bv.y;
            *reinterpret_cast<float2*>(ns + g * NSY + c0)       = o0;
            *reinterpret_cast<float2*>(ns + (g + 8) * NSY + c0) = o1;
        }
    }
    __syncthreads();

    // zero the 8 pad rows of both mixed planes (once; never overwritten)
    for (int i = tid; i < 8 * MPLW; i += THREADS) {
        mh[136 * MPLW + i] = 0;
        ml[136 * MPLW + i] = 0;
    }
    // (ordered before first GEMM read by gat_layer's internal __syncthreads)

    // ================= GAT1, GAT2 (+fused coord projection) =================
    gat_layer<false>(ns, mh, ml, adjs, g_adj,       g_wgp,       bg1, Wc, bc,
                     nullptr, tid);
    gat_layer<true >(ns, mh, ml, adjs, g_adj + 289, g_wgp + 256, bg2, Wc, bc,
                     out + (size_t)tok0 * NN * 2, tid);
}

extern "C" void kernel_launch(void* const* d_in, const int* in_sizes, int n_in,
                              void* d_out, int out_size) {
    const float* x    = (const float*)d_in[0];
    const float* W1   = (const float*)d_in[1];
    const float* b1   = (const float*)d_in[2];
    const float* W2   = (const float*)d_in[3];
    const float* b2   = (const float*)d_in[4];
    const float* adj1 = (const float*)d_in[5];
    const float* Wg1  = (const float*)d_in[6];
    const float* bg1  = (const float*)d_in[7];
    const float* adj2 = (const float*)d_in[8];
    const float* Wg2  = (const float*)d_in[9];
    const float* bg2  = (const float*)d_in[10];
    const float* Wc   = (const float*)d_in[11];
    const float* bc   = (const float*)d_in[12];
    float* out = (float*)d_out;

    split_weights_kernel<<<171, 256>>>(W1, W2, Wg1, Wg2, adj1, adj2);

    const size_t smem = SMEM_FLOATS * sizeof(float);
    cudaFuncSetAttribute((const void*)biogat_kernel,
                         cudaFuncAttributeMaxDynamicSharedMemorySize, (int)smem);
    biogat_kernel<<<NCTA, THREADS, smem>>>(x, b1, b2, bg1, bg2, Wc, bc, out);
}

// round 17
// speedup vs baseline: 1.2446x; 1.2446x over previous
#include <cuda_runtime.h>
#include <math.h>
#include <stdint.h>

#define THREADS 512
#define TT      64
#define N_TOK   65536
#define NCTA    (N_TOK / TT)     // 1024
#define DM      128
#define HID     256
#define NN      17
#define NF      32
#define ND      544              // 17*32

#define NSY  548                 // ns row stride (floats)
#define HPLW 132                 // h-plane row stride (u32 words)
#define XPW  68                  // x-plane row stride (u32 words)
#define MPLW 18                  // mixed-plane row stride (u32 words; 16 + 2 pad)

// ---- smem layout (floats) ----
// ns [64][548] | plane region (19584: h hi/lo planes, later mixed hi/lo planes) | adj
#define OFF_NS   0
#define SZ_NS    (TT * NSY)            // 35072
#define OFF_WB   (OFF_NS + SZ_NS)      // 35072
#define SZ_WB    19584                 // >= 2*64*132 (h) and == 2*544*18 (mixed)
#define OFF_ADJ  (OFF_WB + SZ_WB)      // 54656
#define SZ_ADJ   292
#define SMEM_FLOATS (OFF_ADJ + SZ_ADJ) // 54948 floats = 219792 B

// pre-split weights in fragment-packed layout: {hi0, hi1, lo0, lo1} per lane
__device__ uint4 g_w1p[16 * 8 * 2 * 32];    // group = (j*8+kc)*2+fi
__device__ uint4 g_w2p[34 * 16 * 2 * 32];   // group = (j*16+kc)*2+fi
__device__ uint4 g_wgp[2 * 2 * 4 * 32];     // group = ((layer*2+kc)*4+nf)
__device__ float g_adj[2 * NN * NN];        // softmaxed adjacency per layer

__device__ __forceinline__ float gelu_f(float v) {
    return 0.5f * v * (1.0f + erff(v * 0.7071067811865476f));
}

// split a k-pair (v0 = even k, v1 = odd k) into packed bf16x2 hi and lo words.
__device__ __forceinline__ void pair_split(float v0, float v1, uint32_t& hi, uint32_t& lo) {
    uint32_t h;
    asm("cvt.rn.bf16x2.f32 %0, %1, %2;" : "=r"(h) : "f"(v1), "f"(v0));
    float h0 = __uint_as_float(h << 16);
    float h1 = __uint_as_float(h & 0xffff0000u);
    asm("cvt.rn.bf16x2.f32 %0, %1, %2;" : "=r"(lo) : "f"(v1 - h1), "f"(v0 - h0));
    hi = h;
}

// m16n8k16 bf16 MMA, fp32 accumulate
__device__ __forceinline__ void mma_bf16(float* d, const uint32_t* a, const uint32_t* b) {
    asm volatile(
        "mma.sync.aligned.m16n8k16.row.col.f32.bf16.bf16.f32 "
        "{%0,%1,%2,%3}, {%4,%5,%6,%7}, {%8,%9}, {%0,%1,%2,%3};"
        : "+f"(d[0]), "+f"(d[1]), "+f"(d[2]), "+f"(d[3])
        : "r"(a[0]), "r"(a[1]), "r"(a[2]), "r"(a[3]), "r"(b[0]), "r"(b[1]));
}

// ---------------- prologue: pack W1/W2/Wg frags + adj softmax ----------------
extern "C" __global__ void __launch_bounds__(256)
split_weights_kernel(const float* __restrict__ W1, const float* __restrict__ W2,
                     const float* __restrict__ Wg1, const float* __restrict__ Wg2,
                     const float* __restrict__ adj1, const float* __restrict__ adj2)
{
    const int idx  = blockIdx.x * 256 + threadIdx.x;
    const int grp  = idx >> 5;
    const int lane = idx & 31;
    const int g    = lane >> 2;
    const int tg   = lane & 3;
    if (grp < 256) {                                   // W1: j(16) kc(8) fi(2)
        const int fi = grp & 1, kc = (grp >> 1) & 7, j = grp >> 4;
        const int col = 16 * j + 8 * fi + g;
        const int k0  = 16 * kc + 2 * tg;
        uint32_t h0, l0, h1, l1;
        pair_split(W1[k0 * HID + col],       W1[(k0 + 1) * HID + col], h0, l0);
        pair_split(W1[(k0 + 8) * HID + col], W1[(k0 + 9) * HID + col], h1, l1);
        uint4 v; v.x = h0; v.y = h1; v.z = l0; v.w = l1;
        g_w1p[grp * 32 + lane] = v;
    } else if (grp < 256 + 1088) {                     // W2: j(34) kc(16) fi(2)
        const int g2 = grp - 256;
        const int fi = g2 & 1, kc = (g2 >> 1) & 15, j = g2 >> 5;
        const int col = 16 * j + 8 * fi + g;
        const int k0  = 16 * kc + 2 * tg;
        uint32_t h0, l0, h1, l1;
        pair_split(W2[(size_t)k0 * ND + col],       W2[(size_t)(k0 + 1) * ND + col], h0, l0);
        pair_split(W2[(size_t)(k0 + 8) * ND + col], W2[(size_t)(k0 + 9) * ND + col], h1, l1);
        uint4 v; v.x = h0; v.y = h1; v.z = l0; v.w = l1;
        g_w2p[g2 * 32 + lane] = v;
    } else if (grp < 1344 + 16) {                      // Wg frags: layer(2) kc(2) nf(4)
        const int gg = grp - 1344;
        const int nf = gg & 3, kc = (gg >> 2) & 1, layer = gg >> 3;
        const float* Wg = layer ? Wg2 : Wg1;
        const int col = 8 * nf + g;
        const int k0  = 16 * kc + 2 * tg;
        uint32_t h0, l0, h1, l1;
        pair_split(Wg[k0 * NF + col],       Wg[(k0 + 1) * NF + col], h0, l0);
        pair_split(Wg[(k0 + 8) * NF + col], Wg[(k0 + 9) * NF + col], h1, l1);
        uint4 v; v.x = h0; v.y = h1; v.z = l0; v.w = l1;
        g_wgp[gg * 32 + lane] = v;
    } else if (grp < 1362) {                           // adj softmax rows
        const int layer = grp - 1360;
        const float* aG = layer ? adj2 : adj1;
        if (lane < NN) {
            float r[NN];
            float mx = -3.0e38f;
            #pragma unroll
            for (int j = 0; j < NN; j++) { r[j] = aG[lane * NN + j]; mx = fmaxf(mx, r[j]); }
            float s = 0.0f;
            #pragma unroll
            for (int j = 0; j < NN; j++) { r[j] = expf(r[j] - mx); s += r[j]; }
            float inv = 1.0f / s;
            #pragma unroll
            for (int j = 0; j < NN; j++) g_adj[layer * 289 + lane * NN + j] = r[j] * inv;
        }
    }
}

// ---------------- GAT layer: mixed (FFMA) + linear (bf16x3 MMA GEMM) ----------------
// Per 32-token half: mixed -> split planes [544 x 32]; GEMM @ Wg[32x32]; epilogue
// fuses bias+gelu+residual (and coord projection when FINAL).
template<bool FINAL>
__device__ __forceinline__ void gat_layer(
    float* __restrict__ ns, uint32_t* __restrict__ mh, uint32_t* __restrict__ ml,
    float* __restrict__ adjs,
    const float* __restrict__ adjP, const uint4* __restrict__ wgp,
    const float* __restrict__ bgG,
    const float* __restrict__ Wc, const float* __restrict__ bc,
    float* __restrict__ outp, int tid)
{
    const int lane = tid & 31;
    const int wid  = tid >> 5;
    const int g    = lane >> 2;
    const int tg   = lane & 3;

    // stage precomputed softmaxed adjacency into smem
    for (int i = tid; i < NN * NN; i += THREADS) adjs[i] = adjP[i];
    __syncthreads();   // adjs ready; also orders previous phase's ns writes

    // mixed-plane slot for this lane's feature pair p = lane>>1
    const int pp   = lane >> 1;
    const int slot = (pp >> 3) * 8 + 2 * (pp & 3) + ((pp & 7) >> 2);

    #pragma unroll 1
    for (int half = 0; half < 2; half++) {
        // ---- mixed: warp's 2 tokens -> split bf16 planes ----
        {
            const int tA  = half * 32 + wid * 2;
            const float* ntA = ns + tA * NSY;
            const float* ntB = ntA + NSY;
            float nrA[NN], nrB[NN];
            #pragma unroll
            for (int j = 0; j < NN; j++) {
                nrA[j] = ntA[j * NF + lane];
                nrB[j] = ntB[j * NF + lane];
            }
            const int rA = (wid * 2) * NN;        // local plane row base, token A
            #pragma unroll 1
            for (int i = 0; i < NN; i++) {
                const float* ar = adjs + i * NN;
                float mA = 0.0f, mB = 0.0f;
                #pragma unroll
                for (int j = 0; j < NN; j++) {
                    const float a = ar[j];
                    mA += a * nrA[j];
                    mB += a * nrB[j];
                }
                const float vA = __shfl_xor_sync(0xffffffffu, mA, 1);
                const float vB = __shfl_xor_sync(0xffffffffu, mB, 1);
                uint32_t hi, lo;
                int row;
                if (lane & 1) { pair_split(vB, mB, hi, lo); row = rA + NN + i; }
                else          { pair_split(mA, vA, hi, lo); row = rA + i; }
                mh[row * MPLW + slot] = hi;
                ml[row * MPLW + slot] = lo;
            }
        }
        __syncthreads();   // planes complete before cross-warp GEMM reads

        // ---- GEMM [544 x 32] @ Wg[32 x 32] (bf16x3) + fused epilogue ----
        {
            // B-frags from prologue-packed g_wgp: kc(2) x nf(4), coalesced LDG.128
            uint32_t bh[2][4][2], bl[2][4][2];
            #pragma unroll
            for (int kc = 0; kc < 2; kc++)
                #pragma unroll
                for (int nf = 0; nf < 4; nf++) {
                    uint4 bw = wgp[(kc * 4 + nf) * 32 + lane];
                    bh[kc][nf][0] = bw.x; bh[kc][nf][1] = bw.y;
                    bl[kc][nf][0] = bw.z; bl[kc][nf][1] = bw.w;
                }
            float bgr[4][2];
            #pragma unroll
            for (int nf = 0; nf < 4; nf++) {
                bgr[nf][0] = bgG[8 * nf + 2 * tg];
                bgr[nf][1] = bgG[8 * nf + 2 * tg + 1];
            }
            float wcr[4][2][2], bc0 = 0.0f, bc1 = 0.0f;
            if (FINAL) {
                #pragma unroll
                for (int nf = 0; nf < 4; nf++)
                    #pragma unroll
                    for (int jj = 0; jj < 2; jj++) {
                        wcr[nf][jj][0] = Wc[(8 * nf + 2 * tg + jj) * 2];
                        wcr[nf][jj][1] = Wc[(8 * nf + 2 * tg + jj) * 2 + 1];
                    }
                bc0 = bc[0]; bc1 = bc[1];
            }

            #pragma unroll 1
            for (int mi = wid; mi < 34; mi += 16) {
                float d[4][4] = {};
                const int r0 = 16 * mi + g;
                #pragma unroll
                for (int kc = 0; kc < 2; kc++) {
                    const int base = kc * 8 + 2 * tg;
                    uint32_t ah[4], al[4];
                    uint2 q0, q1;
                    q0 = *reinterpret_cast<const uint2*>(mh + r0 * MPLW + base);
                    q1 = *reinterpret_cast<const uint2*>(mh + (r0 + 8) * MPLW + base);
                    ah[0] = q0.x; ah[2] = q0.y; ah[1] = q1.x; ah[3] = q1.y;
                    q0 = *reinterpret_cast<const uint2*>(ml + r0 * MPLW + base);
                    q1 = *reinterpret_cast<const uint2*>(ml + (r0 + 8) * MPLW + base);
                    al[0] = q0.x; al[2] = q0.y; al[1] = q1.x; al[3] = q1.y;
                    #pragma unroll
                    for (int nf = 0; nf < 4; nf++) {
                        mma_bf16(d[nf], ah, bh[kc][nf]);
                        mma_bf16(d[nf], al, bh[kc][nf]);
                        mma_bf16(d[nf], ah, bl[kc][nf]);
                    }
                }
                // epilogue: rows rg0 (d[.][0..1]) and rg0+8 (d[.][2..3])
                const int rg0 = half * 544 + r0;
                const int rg1 = rg0 + 8;
                const int t0i = rg0 / NN, i0 = rg0 - t0i * NN;
                const int t1i = rg1 / NN, i1 = rg1 - t1i * NN;
                float* p0base = ns + t0i * NSY + i0 * NF;
                float* p1base = ns + t1i * NSY + i1 * NF;
                if (!FINAL) {
                    #pragma unroll
                    for (int nf = 0; nf < 4; nf++) {
                        const int c0 = 8 * nf + 2 * tg;
                        float2 rv0 = *reinterpret_cast<float2*>(p0base + c0);
                        float2 rv1 = *reinterpret_cast<float2*>(p1base + c0);
                        float2 o0, o1;
                        o0.x = gelu_f(d[nf][0] + bgr[nf][0]) + rv0.x;
                        o0.y = gelu_f(d[nf][1] + bgr[nf][1]) + rv0.y;
                        o1.x = gelu_f(d[nf][2] + bgr[nf][0]) + rv1.x;
                        o1.y = gelu_f(d[nf][3] + bgr[nf][1]) + rv1.y;
                        *reinterpret_cast<float2*>(p0base + c0) = o0;
                        *reinterpret_cast<float2*>(p1base + c0) = o1;
                    }
                } else {
                    float s00 = 0.0f, s01 = 0.0f, s10 = 0.0f, s11 = 0.0f;
                    #pragma unroll
                    for (int nf = 0; nf < 4; nf++) {
                        const int c0 = 8 * nf + 2 * tg;
                        float2 rv0 = *reinterpret_cast<float2*>(p0base + c0);
                        float2 rv1 = *reinterpret_cast<float2*>(p1base + c0);
                        const float v0 = gelu_f(d[nf][0] + bgr[nf][0]) + rv0.x;
                        const float v1 = gelu_f(d[nf][1] + bgr[nf][1]) + rv0.y;
                        const float v2 = gelu_f(d[nf][2] + bgr[nf][0]) + rv1.x;
                        const float v3 = gelu_f(d[nf][3] + bgr[nf][1]) + rv1.y;
                        s00 += v0 * wcr[nf][0][0] + v1 * wcr[nf][1][0];
                        s01 += v0 * wcr[nf][0][1] + v1 * wcr[nf][1][1];
                        s10 += v2 * wcr[nf][0][0] + v3 * wcr[nf][1][0];
                        s11 += v2 * wcr[nf][0][1] + v3 * wcr[nf][1][1];
                    }
                    // reduce over tg (lane bits 0-1) within each quad
                    #pragma unroll
                    for (int off = 1; off <= 2; off <<= 1) {
                        s00 += __shfl_xor_sync(0xffffffffu, s00, off);
                        s01 += __shfl_xor_sync(0xffffffffu, s01, off);
                        s10 += __shfl_xor_sync(0xffffffffu, s10, off);
                        s11 += __shfl_xor_sync(0xffffffffu, s11, off);
                    }
                    if (tg == 0) {
                        float2 o0; o0.x = s00 + bc0; o0.y = s01 + bc1;
                        float2 o1; o1.x = s10 + bc0; o1.y = s11 + bc1;
                        *reinterpret_cast<float2*>(outp + t0i * (NN * 2) + i0 * 2) = o0;
                        *reinterpret_cast<float2*>(outp + t1i * (NN * 2) + i1 * 2) = o1;
                    }
                }
            }
        }
        __syncthreads();   // all GEMM reads done before next half overwrites planes
    }
}

// ---------------- fused main kernel ----------------
extern "C" __global__ void __launch_bounds__(THREADS, 1)
biogat_kernel(const float* __restrict__ x,
              const float* __restrict__ b1,  const float* __restrict__ b2,
              const float* __restrict__ bg1, const float* __restrict__ bg2,
              const float* __restrict__ Wc,  const float* __restrict__ bc,
              float* __restrict__ out)
{
    extern __shared__ float sh[];
    float*    ns   = sh + OFF_NS;
    float*    wbr  = sh + OFF_WB;
    float*    adjs = sh + OFF_ADJ;

    // h hi/lo planes alias the head of the plane region (dead once GAT starts)
    uint32_t* hh = reinterpret_cast<uint32_t*>(wbr);
    uint32_t* hl = hh + TT * HPLW;
    // mixed hi/lo planes alias the same region during GAT (544*18 each)
    uint32_t* mh = reinterpret_cast<uint32_t*>(wbr);
    uint32_t* ml = mh + 544 * MPLW;

    // x planes alias the ns region (dead before phase 2 writes ns)
    uint32_t* xh = reinterpret_cast<uint32_t*>(sh + OFF_NS);
    uint32_t* xl = xh + TT * XPW;

    const int tid  = threadIdx.x;
    const int w    = tid >> 5;    // 0..15
    const int lane = tid & 31;
    const int g    = lane >> 2;
    const int tg   = lane & 3;
    const int tok0 = blockIdx.x * TT;

    // ---- stage + split x ONCE into fragment-permuted bf16 hi/lo planes ----
    {
        const float2* xg = reinterpret_cast<const float2*>(x + (size_t)tok0 * DM);
        #pragma unroll
        for (int it = 0; it < (TT * 64) / THREADS; it++) {
            const int p = tid + it * THREADS;
            const int r = p >> 6, q = p & 63;
            float2 v = xg[p];
            uint32_t hi, lo; pair_split(v.x, v.y, hi, lo);
            const int slot = (q >> 3) * 8 + 2 * (q & 3) + ((q & 7) >> 2);
            xh[r * XPW + slot] = hi;
            xl[r * XPW + slot] = lo;
        }
    }
    __syncthreads();

    // ================= phase 1: h = gelu(x @ W1 + b1) =================
    {
        const int n0 = 16 * w;
        float d[4][2][4] = {};
        #pragma unroll 1
        for (int kc = 0; kc < 8; kc++) {
            uint32_t bh[2][2], bl[2][2];
            #pragma unroll
            for (int fi = 0; fi < 2; fi++) {
                uint4 bw = g_w1p[((w * 8 + kc) * 2 + fi) * 32 + lane];
                bh[fi][0] = bw.x; bh[fi][1] = bw.y;
                bl[fi][0] = bw.z; bl[fi][1] = bw.w;
            }
            #pragma unroll
            for (int mi = 0; mi < 4; mi++) {
                const int r0 = 16 * mi + g;
                const int base = kc * 8 + 2 * tg;
                uint32_t ah[4], al[4];
                uint2 t0, t1;
                t0 = *reinterpret_cast<const uint2*>(xh + r0 * XPW + base);
                t1 = *reinterpret_cast<const uint2*>(xh + (r0 + 8) * XPW + base);
                ah[0] = t0.x; ah[2] = t0.y; ah[1] = t1.x; ah[3] = t1.y;
                t0 = *reinterpret_cast<const uint2*>(xl + r0 * XPW + base);
                t1 = *reinterpret_cast<const uint2*>(xl + (r0 + 8) * XPW + base);
                al[0] = t0.x; al[2] = t0.y; al[1] = t1.x; al[3] = t1.y;
                #pragma unroll
                for (int fi = 0; fi < 2; fi++) {
                    mma_bf16(d[mi][fi], ah, bh[fi]);
                    mma_bf16(d[mi][fi], al, bh[fi]);
                    mma_bf16(d[mi][fi], ah, bl[fi]);
                }
            }
        }
        const float2 bv0 = *reinterpret_cast<const float2*>(b1 + n0 + 2 * tg);
        const float2 bv1 = *reinterpret_cast<const float2*>(b1 + n0 + 8 + 2 * tg);
        #pragma unroll
        for (int mi = 0; mi < 4; mi++) {
            #pragma unroll
            for (int half = 0; half < 2; half++) {
                const int row = 16 * mi + g + 8 * half;
                uint32_t hw0, lw0, hw1, lw1;
                pair_split(gelu_f(d[mi][0][2*half]   + bv0.x),
                           gelu_f(d[mi][0][2*half+1] + bv0.y), hw0, lw0);
                pair_split(gelu_f(d[mi][1][2*half]   + bv1.x),
                           gelu_f(d[mi][1][2*half+1] + bv1.y), hw1, lw1);
                const int widx = row * HPLW + w * 8 + 2 * tg;
                uint2 hv; hv.x = hw0; hv.y = hw1;
                uint2 lv; lv.x = lw0; lv.y = lw1;
                *reinterpret_cast<uint2*>(hh + widx) = hv;
                *reinterpret_cast<uint2*>(hl + widx) = lv;
            }
        }
    }
    __syncthreads();

    // ================= phase 2: nodes = h @ W2 + b2 =================
    #pragma unroll 1
    for (int j = w; j < 34; j += 16) {
        const int n0 = 16 * j;
        float d[4][2][4] = {};
        #pragma unroll 1
        for (int kc = 0; kc < 16; kc++) {
            uint32_t bh[2][2], bl[2][2];
            #pragma unroll
            for (int nf = 0; nf < 2; nf++) {
                uint4 bw = g_w2p[((j * 16 + kc) * 2 + nf) * 32 + lane];
                bh[nf][0] = bw.x; bh[nf][1] = bw.y;
                bl[nf][0] = bw.z; bl[nf][1] = bw.w;
            }
            #pragma unroll
            for (int mi = 0; mi < 4; mi++) {
                const int r0 = 16 * mi + g;
                const int base = kc * 8 + 2 * tg;
                uint32_t ah[4], al[4];
                uint2 t0, t1;
                t0 = *reinterpret_cast<const uint2*>(hh + r0 * HPLW + base);
                t1 = *reinterpret_cast<const uint2*>(hh + (r0 + 8) * HPLW + base);
                ah[0] = t0.x; ah[2] = t0.y; ah[1] = t1.x; ah[3] = t1.y;
                t0 = *reinterpret_cast<const uint2*>(hl + r0 * HPLW + base);
                t1 = *reinterpret_cast<const uint2*>(hl + (r0 + 8) * HPLW + base);
                al[0] = t0.x; al[2] = t0.y; al[1] = t1.x; al[3] = t1.y;
                #pragma unroll
                for (int nf = 0; nf < 2; nf++) {
                    mma_bf16(d[mi][nf], ah, bh[nf]);
                    mma_bf16(d[mi][nf], al, bh[nf]);
                    mma_bf16(d[mi][nf], ah, bl[nf]);
                }
            }
        }
        #pragma unroll
        for (int nf = 0; nf < 2; nf++) {
            const int c0 = n0 + 8 * nf + 2 * tg;
            const float2 bv = *reinterpret_cast<const float2*>(b2 + c0);
            #pragma unroll
            for (int mi = 0; mi < 4; mi++) {
                const int r0 = 16 * mi + g;
                float2 o0, o1;
                o0.x = d[mi][nf][0] + bv.x;
                o0.y = d[mi][nf][1] + bv.y;
                o1.x = d[mi][nf][2] + bv.x;
                o1.y = d[mi][nf][3] + bv.y;
                *reinterpret_cast<float2*>(ns + r0 * NSY + c0)       = o0;
                *reinterpret_cast<float2*>(ns + (r0 + 8) * NSY + c0) = o1;
            }
        }
    }
    __syncthreads();

    // ================= GAT1, GAT2 (+fused coord projection) =================
    gat_layer<false>(ns, mh, ml, adjs, g_adj,       g_wgp,       bg1, Wc, bc,
                     nullptr, tid);
    gat_layer<true >(ns, mh, ml, adjs, g_adj + 289, g_wgp + 256, bg2, Wc, bc,
                     out + (size_t)tok0 * NN * 2, tid);
}

extern "C" void kernel_launch(void* const* d_in, const int* in_sizes, int n_in,
                              void* d_out, int out_size) {
    const float* x    = (const float*)d_in[0];
    const float* W1   = (const float*)d_in[1];
    const float* b1   = (const float*)d_in[2];
    const float* W2   = (const float*)d_in[3];
    const float* b2   = (const float*)d_in[4];
    const float* adj1 = (const float*)d_in[5];
    const float* Wg1  = (const float*)d_in[6];
    const float* bg1  = (const float*)d_in[7];
    const float* adj2 = (const float*)d_in[8];
    const float* Wg2  = (const float*)d_in[9];
    const float* bg2  = (const float*)d_in[10];
    const float* Wc   = (const float*)d_in[11];
    const float* bc   = (const float*)d_in[12];
    float* out = (float*)d_out;

    split_weights_kernel<<<171, 256>>>(W1, W2, Wg1, Wg2, adj1, adj2);

    const size_t smem = SMEM_FLOATS * sizeof(float);
    cudaFuncSetAttribute((const void*)biogat_kernel,
                         cudaFuncAttributeMaxDynamicSharedMemorySize, (int)smem);
    biogat_kernel<<<NCTA, THREADS, smem>>>(x, b1, b2, bg1, bg2, Wc, bc, out);
}